// round 1
// baseline (speedup 1.0000x reference)
#include <cuda_runtime.h>
#include <cstdint>

#define B 8
#define F 4000
#define S 512
#define E 128
#define H 128

#define SSQ   (S * S)          // 262144
#define BSS   (B * S * S)      // 2097152
#define BSE   (B * S * E)      // 524288

#define KSPLIT 4
#define KCH    (F / KSPLIT)    // 1000
#define KB     20

// ---------------- device scratch (no allocations allowed) ----------------
__device__ float               g_partial[KSPLIT][BSE];   // split-K partials (8 MB)
__device__ float               g_emb[BSE];               // tanh(embedded), layout [b][s][e]
__device__ unsigned            g_keys[S][2];             // per-step threefry keys
__device__ unsigned long long  g_keep[B * S][8];         // top-8 keep bitmask per (b,i)
__device__ unsigned long long  g_samp0[S][B][8];         // bern & keep bits per step
__device__ unsigned long long  g_sel[S][B][8];           // final samp per step (prev_idxs)
__device__ unsigned long long  g_mask[B][S][8];          // final ancestor mask bits

// ---------------- threefry2x32 (exact JAX semantics) ----------------
__device__ __forceinline__ unsigned rotl32(unsigned v, int d) {
    return (v << d) | (v >> (32 - d));
}

__device__ __forceinline__ void threefry2x32(unsigned k0, unsigned k1,
                                             unsigned x0, unsigned x1,
                                             unsigned& o0, unsigned& o1) {
    unsigned ks0 = k0, ks1 = k1, ks2 = k0 ^ k1 ^ 0x1BD11BDAu;
    x0 += ks0; x1 += ks1;
#define TF_RND(r) { x0 += x1; x1 = rotl32(x1, r); x1 ^= x0; }
    TF_RND(13) TF_RND(15) TF_RND(26) TF_RND(6)
    x0 += ks1; x1 += ks2 + 1u;
    TF_RND(17) TF_RND(29) TF_RND(16) TF_RND(24)
    x0 += ks2; x1 += ks0 + 2u;
    TF_RND(13) TF_RND(15) TF_RND(26) TF_RND(6)
    x0 += ks0; x1 += ks1 + 3u;
    TF_RND(17) TF_RND(29) TF_RND(16) TF_RND(24)
    x0 += ks1; x1 += ks2 + 4u;
    TF_RND(13) TF_RND(15) TF_RND(26) TF_RND(6)
    x0 += ks2; x1 += ks0 + 5u;
#undef TF_RND
    o0 = x0; o1 = x1;
}

// per-step keys: foldlike split of key(42) = (0, 42); key_t = threefry(key, (0, t))
__global__ void k_keys() {
    int t = threadIdx.x;
    unsigned o0, o1;
    threefry2x32(0u, 42u, 0u, (unsigned)t, o0, o1);
    g_keys[t][0] = o0;
    g_keys[t][1] = o1;
}

// ---------------- GEMM1: pre-tanh embedded, split-K ----------------
// C[b, s, e] = sum_f inputs[b, f, s] * emb[f, e]
__global__ __launch_bounds__(256, 2)
void k_gemm1(const float* __restrict__ inp, const float* __restrict__ emb) {
    int stile = blockIdx.x;      // 0..7  -> s0 = 64*stile
    int b     = blockIdx.y;      // 0..7
    int ks    = blockIdx.z;      // 0..KSPLIT-1
    int t     = threadIdx.x;     // 0..255

    __shared__ float As[KB][64];
    __shared__ float Bs[KB][128];

    int s0 = stile * 64;
    int f0 = ks * KCH;
    int te = (t & 15) * 8;       // e offset within 128
    int ts = (t >> 4) * 4;       // s offset within 64

    float acc[4][8];
#pragma unroll
    for (int i = 0; i < 4; ++i)
#pragma unroll
        for (int j = 0; j < 8; ++j) acc[i][j] = 0.f;

    const float* inp_b = inp + (size_t)b * F * S;

    int lsA = t & 63, lkA = t >> 6;    // A loader: s, k-base
    int leB = t & 127, lkB = t >> 7;   // B loader: e, k-base

    for (int kb = 0; kb < KCH; kb += KB) {
#pragma unroll
        for (int p = 0; p < 5; ++p)
            As[lkA + 4 * p][lsA] = inp_b[(size_t)(f0 + kb + lkA + 4 * p) * S + s0 + lsA];
#pragma unroll
        for (int p = 0; p < 10; ++p)
            Bs[lkB + 2 * p][leB] = emb[(size_t)(f0 + kb + lkB + 2 * p) * E + leB];
        __syncthreads();

#pragma unroll
        for (int k = 0; k < KB; ++k) {
            float4 a4  = *reinterpret_cast<const float4*>(&As[k][ts]);
            float4 b4a = *reinterpret_cast<const float4*>(&Bs[k][te]);
            float4 b4b = *reinterpret_cast<const float4*>(&Bs[k][te + 4]);
            float av[4] = {a4.x, a4.y, a4.z, a4.w};
            float bv[8] = {b4a.x, b4a.y, b4a.z, b4a.w, b4b.x, b4b.y, b4b.z, b4b.w};
#pragma unroll
            for (int i = 0; i < 4; ++i)
#pragma unroll
                for (int j = 0; j < 8; ++j)
                    acc[i][j] = fmaf(av[i], bv[j], acc[i][j]);
        }
        __syncthreads();
    }

#pragma unroll
    for (int i = 0; i < 4; ++i) {
        float* dst = &g_partial[ks][(size_t)(b * S + s0 + ts + i) * E + te];
        float4 v0 = make_float4(acc[i][0], acc[i][1], acc[i][2], acc[i][3]);
        float4 v1 = make_float4(acc[i][4], acc[i][5], acc[i][6], acc[i][7]);
        *reinterpret_cast<float4*>(dst)     = v0;
        *reinterpret_cast<float4*>(dst + 4) = v1;
    }
}

// fixed-order split-K reduction + tanh
__global__ void k_reduce_tanh() {
    int n = blockIdx.x * blockDim.x + threadIdx.x;
    if (n >= BSE) return;
    float s = g_partial[0][n] + g_partial[1][n] + g_partial[2][n] + g_partial[3][n];
    g_emb[n] = tanhf(s);
}

// ---------------- GEMM2 + sigmoid + clip -> probs (output region 0) ---------------
// logits[b,i,o] = sum_h g_emb[b,i,h] * W[i,h,o] + bias[i,o]
__global__ __launch_bounds__(512, 2)
void k_probs(const float* __restrict__ W, const float* __restrict__ bias,
             float* __restrict__ out) {
    int i = blockIdx.x;       // 0..511
    int o = threadIdx.x;      // 0..511

    __shared__ float es[H * B];   // es[h*8 + b]
#pragma unroll
    for (int q = 0; q < 2; ++q) {
        int m = threadIdx.x + q * 512;
        int bb = m >> 7, h = m & 127;
        es[h * 8 + bb] = g_emb[(size_t)(bb * S + i) * H + h];
    }
    __syncthreads();

    float acc[8];
#pragma unroll
    for (int b = 0; b < 8; ++b) acc[b] = 0.f;

    const float* Wp = W + (size_t)i * H * S + o;
#pragma unroll 8
    for (int h = 0; h < H; ++h) {
        float w = Wp[(size_t)h * S];
        float4 eA = *reinterpret_cast<const float4*>(&es[h * 8]);
        float4 eB = *reinterpret_cast<const float4*>(&es[h * 8 + 4]);
        acc[0] = fmaf(w, eA.x, acc[0]);
        acc[1] = fmaf(w, eA.y, acc[1]);
        acc[2] = fmaf(w, eA.z, acc[2]);
        acc[3] = fmaf(w, eA.w, acc[3]);
        acc[4] = fmaf(w, eB.x, acc[4]);
        acc[5] = fmaf(w, eB.y, acc[5]);
        acc[6] = fmaf(w, eB.z, acc[6]);
        acc[7] = fmaf(w, eB.w, acc[7]);
    }

    float bi = bias[(size_t)i * S + o];
#pragma unroll
    for (int b = 0; b < 8; ++b) {
        float x = acc[b] + bi;
        float p = 1.0f / (1.0f + expf(-x));
        p = fminf(fmaxf(p, 1e-4f), 0.9999f);
        out[(size_t)(b * S + i) * S + o] = p;
    }
}

// ---------------- top-8 per (b, i) row, XLA-stable tie-break ----------------
__global__ void k_topk(const float* __restrict__ probs) {
    int warp = blockIdx.x * (blockDim.x >> 5) + (threadIdx.x >> 5);  // 0..4095
    int lane = threadIdx.x & 31;
    int b = warp >> 9;
    int i = warp & 511;
    const float* row = probs + (size_t)(b * S + i) * S;

    float v[16];
#pragma unroll
    for (int j = 0; j < 16; ++j) v[j] = row[lane + 32 * j];

    unsigned taken = 0;
    unsigned long long keep[8] = {0, 0, 0, 0, 0, 0, 0, 0};

    for (int r = 0; r < 8; ++r) {
        float bestv = -1e30f;
        int   besto = 1 << 30;
#pragma unroll
        for (int j = 0; j < 16; ++j) {
            if (!((taken >> j) & 1u)) {
                int o = lane + 32 * j;
                // j ascending => o ascending within lane; strict > keeps lowest o on ties
                if (v[j] > bestv) { bestv = v[j]; besto = o; }
            }
        }
#pragma unroll
        for (int d = 16; d; d >>= 1) {
            float ov = __shfl_xor_sync(0xFFFFFFFFu, bestv, d);
            int   oo = __shfl_xor_sync(0xFFFFFFFFu, besto, d);
            if (ov > bestv || (ov == bestv && oo < besto)) { bestv = ov; besto = oo; }
        }
        if ((besto & 31) == lane) taken |= 1u << (besto >> 5);
        if (lane == 0) keep[besto >> 6] |= 1ull << (besto & 63);
    }
    if (lane == 0) {
#pragma unroll
        for (int w = 0; w < 8; ++w) g_keep[b * S + i][w] = keep[w];
    }
}

// ---------------- bernoulli & keep -> samp0 bits per step ----------------
// partitionable threefry draw: element l (flat over (B,S)):
//   (o0,o1) = threefry(keys[t], (0, l)); bits = o0 ^ o1; u = bitcast((bits>>9)|0x3f800000)-1
__global__ void k_sample(const float* __restrict__ probs) {
    int t = blockIdx.x;       // step
    int j = threadIdx.x;      // 0..511
    __shared__ unsigned long long sh[B * 8];
    if (j < 64) sh[j] = 0ull;
    __syncthreads();

    unsigned k0 = g_keys[t][0], k1 = g_keys[t][1];
#pragma unroll
    for (int q = 0; q < 8; ++q) {
        int l = j + q * 512;
        unsigned o0, o1;
        threefry2x32(k0, k1, 0u, (unsigned)l, o0, o1);
        unsigned bits = o0 ^ o1;
        float u = __uint_as_float((bits >> 9) | 0x3f800000u) - 1.0f;
        int b = l >> 9, s = l & 511;
        float p = probs[(size_t)(b * S + t) * S + s];
        bool keep = (g_keep[b * S + t][s >> 6] >> (s & 63)) & 1ull;
        if (keep && (u < p))
            atomicOr(&sh[b * 8 + (s >> 6)], 1ull << (s & 63));
    }
    __syncthreads();
    if (j < 64) ((unsigned long long*)&g_samp0[t][0][0])[j] = sh[j];
}

// ---------------- sequential acyclic-mask scan (bit-packed) ----------------
__global__ __launch_bounds__(512, 1)
void k_scan() {
    int b = blockIdx.x;       // batch
    int a = threadIdx.x;      // row (potential ancestor)

    unsigned long long row[8] = {0, 0, 0, 0, 0, 0, 0, 0};
    __shared__ unsigned long long smp[8];
    __shared__ unsigned long long rsh[8];

    for (int t = 0; t < S; ++t) {
        if (a == t) {
#pragma unroll
            for (int w = 0; w < 8; ++w) {
                unsigned long long s = g_samp0[t][b][w] & ~row[w];
                if (w == (t >> 6)) s &= ~(1ull << (t & 63));
                smp[w] = s;
                rsh[w] = row[w];
            }
        }
        __syncthreads();

        unsigned long long anc = 0;
#pragma unroll
        for (int w = 0; w < 8; ++w) anc |= row[w] & smp[w];

        bool col = (anc != 0ull)
                 || (((row[t >> 6] >> (t & 63)) & 1ull) != 0ull)
                 || (((smp[a >> 6] >> (a & 63)) & 1ull) != 0ull);

        if (a < 8) g_sel[t][b][a] = smp[a];

        if (col) {
#pragma unroll
            for (int w = 0; w < 8; ++w) row[w] |= rsh[w];
            row[t >> 6] |= 1ull << (t & 63);
        }
        __syncthreads();
    }

#pragma unroll
    for (int w = 0; w < 8; ++w) g_mask[b][a][w] = row[w];
}

// ---------------- expand bool bitsets to float output regions ----------------
__global__ void k_expand(float* __restrict__ out) {
    int n = blockIdx.x * blockDim.x + threadIdx.x;
    if (n >= BSS) return;
    int c   = n & 511;
    int mid = (n >> 9) & 511;
    int b   = n >> 18;
    out[BSS + n]     = 0.0f;  // prev_probs_2
    out[2 * BSS + n] = (float)((g_sel[mid][b][c >> 6] >> (c & 63)) & 1ull);
    out[3 * BSS + n] = (float)((g_mask[b][mid][c >> 6] >> (c & 63)) & 1ull);
}

// ---------------- launch ----------------
extern "C" void kernel_launch(void* const* d_in, const int* in_sizes, int n_in,
                              void* d_out, int out_size) {
    const float* inp  = (const float*)d_in[0];   // (B, F, S)
    const float* emb  = (const float*)d_in[1];   // (F, E)
    const float* W    = (const float*)d_in[2];   // (S, H, S)
    const float* bias = (const float*)d_in[3];   // (S, S)
    float* out = (float*)d_out;

    k_keys<<<1, 512>>>();

    dim3 g1(8, 8, KSPLIT);
    k_gemm1<<<g1, 256>>>(inp, emb);
    k_reduce_tanh<<<(BSE + 255) / 256, 256>>>();

    k_probs<<<512, 512>>>(W, bias, out);
    k_topk<<<512, 256>>>(out);
    k_sample<<<512, 512>>>(out);
    k_scan<<<B, 512>>>();
    k_expand<<<(BSS + 255) / 256, 256>>>(out);
}